// round 2
// baseline (speedup 1.0000x reference)
#include <cuda_runtime.h>

// ShiftWindowMSA fused kernel for GB300 (sm_103a)
// B=4, H=W=224, C=96, window=7 (N=49), shift=3, heads=3 (hd=32)
// 224 % 7 == 0 -> no padding, Hp=Wp=224, 32x32 windows, Bn = 4*1024 = 4096.

#define WIN     7
#define NTOK    49          // window tokens
#define CH      96          // channels
#define NH      3           // heads
#define HD      32          // head dim
#define RS      97          // smem row stride (conflict-free padding)
#define HP      224
#define NWROW   32          // windows per spatial dim
#define NWIN    1024        // windows per batch image
#define THREADS 256

// smem layout (floats)
#define OFF_X    0                      // 49x96 (stride 97) = 4753 ; attn overlays [0,7203)
#define OFF_SX   4753                   // 49x96
#define OFF_K    9506                   // 49x96
#define OFF_V    14259                  // 49x96
#define OFF_Q    19012                  // 49x96 (reused as AV result)
#define OFF_WT   23765                  // 32x96 weight tile (stride 97) = 3104
#define OFF_BIAS 26869                  // 169*3 = 507 rel-pos bias table
#define SMEM_FLOATS 27376
#define SMEM_BYTES  (SMEM_FLOATS * 4)

__global__ __launch_bounds__(THREADS, 2)
void swin_msa_kernel(const float* __restrict__ query,
                     const float* __restrict__ skipq,
                     const float* __restrict__ qkv_w,
                     const float* __restrict__ qkv_b,
                     const float* __restrict__ skip_w,
                     const float* __restrict__ skip_b,
                     const float* __restrict__ proj_w,
                     const float* __restrict__ proj_b,
                     const float* __restrict__ btab,
                     float* __restrict__ out)
{
    extern __shared__ float sm[];
    __shared__ int fval[NTOK];    // rel-pos helper: 13*(n/7) + n%7
    __shared__ int regid[NTOK];   // shift-mask region id
    __shared__ int rowoff[NTOK];  // gmem element offset of token row (same for load & store)

    const int t   = threadIdx.x;
    const int blk = blockIdx.x;
    const int b   = blk >> 10;        // batch
    const int wi  = blk & 1023;       // window index within image
    const int wr  = wi >> 5;          // window row
    const int wc  = wi & 31;          // window col

    // ---- per-token precompute ----
    if (t < NTOK) {
        int r = t / 7, c = t - r * 7;
        fval[t] = 13 * r + c;
        int hg = wr * 7 + r;          // shifted-frame coords
        int wg = wc * 7 + c;
        // region boundaries: [0,217) [217,221) [221,224)   (w=7, s=3)
        int rh = (hg < 217) ? 0 : ((hg < 221) ? 1 : 2);
        int rw = (wg < 217) ? 0 : ((wg < 221) ? 1 : 2);
        regid[t] = rh * 3 + rw;
        // roll(-3) on load == roll(+3) on store: src == dst offset
        int hs = hg + 3; if (hs >= HP) hs -= HP;
        int ws = wg + 3; if (ws >= HP) ws -= HP;
        rowoff[t] = (b * (HP * HP) + hs * HP + ws) * CH;
    }
    for (int i = t; i < 507; i += THREADS) sm[OFF_BIAS + i] = btab[i];
    __syncthreads();

    // ---- load x (for K,V) and sx (for Q) windows into smem ----
    {
        const int warp = t >> 5, lane = t & 31;
        for (int n = warp; n < NTOK; n += 8) {
            if (lane < 24) {
                const int base = rowoff[n];
                float4 xv = *(const float4*)(query + base + lane * 4);
                float4 sv = *(const float4*)(skipq + base + lane * 4);
                int so = n * RS + lane * 4;
                sm[OFF_X + so + 0] = xv.x; sm[OFF_X + so + 1] = xv.y;
                sm[OFF_X + so + 2] = xv.z; sm[OFF_X + so + 3] = xv.w;
                sm[OFF_SX + so + 0] = sv.x; sm[OFF_SX + so + 1] = sv.y;
                sm[OFF_SX + so + 2] = sv.z; sm[OFF_SX + so + 3] = sv.w;
            }
        }
    }

    const int tj = t & 31;   // output column lane within 32-wide tile
    const int tn = t >> 5;   // row group 0..7 -> rows tn, tn+8, ..., tn+48

    // ---- KV GEMM: kv[n][j] = dot(x[n,:], qkv_w[j,:]) + qkv_b[j], j in [0,192) ----
    // j < 96 -> K column j ; j >= 96 -> V column j-96
    for (int jt = 0; jt < 6; ++jt) {
        __syncthreads();
        for (int i = t; i < 32 * 96; i += THREADS)
            sm[OFF_WT + (i / 96) * RS + (i % 96)] = qkv_w[jt * 32 * 96 + i];
        __syncthreads();
        const int j = jt * 32 + tj;
        float acc[7];
        const float bj = qkv_b[j];
        #pragma unroll
        for (int i = 0; i < 7; ++i) acc[i] = bj;
        #pragma unroll 4
        for (int cc = 0; cc < 96; ++cc) {
            const float wv = sm[OFF_WT + tj * RS + cc];
            #pragma unroll
            for (int i = 0; i < 7; ++i)
                acc[i] += sm[OFF_X + (tn + 8 * i) * RS + cc] * wv;  // OOB rows read junk smem, not stored
        }
        const int dstcol = (jt < 3) ? (OFF_K + j) : (OFF_V + (j - 96));
        #pragma unroll
        for (int i = 0; i < 7; ++i) {
            const int n = tn + 8 * i;
            if (n < NTOK) sm[dstcol + n * RS] = acc[i];
        }
    }

    // ---- Q GEMM: q[n][j] = dot(sx[n,:], skip_w[j,:]) + skip_b[j] ----
    for (int jt = 0; jt < 3; ++jt) {
        __syncthreads();
        for (int i = t; i < 32 * 96; i += THREADS)
            sm[OFF_WT + (i / 96) * RS + (i % 96)] = skip_w[jt * 32 * 96 + i];
        __syncthreads();
        const int j = jt * 32 + tj;
        float acc[7];
        const float bj = skip_b[j];
        #pragma unroll
        for (int i = 0; i < 7; ++i) acc[i] = bj;
        #pragma unroll 4
        for (int cc = 0; cc < 96; ++cc) {
            const float wv = sm[OFF_WT + tj * RS + cc];
            #pragma unroll
            for (int i = 0; i < 7; ++i)
                acc[i] += sm[OFF_SX + (tn + 8 * i) * RS + cc] * wv;
        }
        #pragma unroll
        for (int i = 0; i < 7; ++i) {
            const int n = tn + 8 * i;
            if (n < NTOK) sm[OFF_Q + n * RS + j] = acc[i];
        }
    }
    __syncthreads();

    // ---- attention scores: attn[(h*49+n)*49+m] = scale*dot(q,k) + bias + mask ----
    // overlays the X/SX region (7203 floats < 9506)
    const float scale = 0.17677669529663687f;  // 1/sqrt(32)
    for (int idx = t; idx < NH * NTOK * NTOK; idx += THREADS) {
        const int h   = idx / (NTOK * NTOK);
        const int rem = idx - h * NTOK * NTOK;
        const int n   = rem / NTOK;
        const int m   = rem - n * NTOK;
        const float* qp = sm + OFF_Q + n * RS + h * HD;
        const float* kp = sm + OFF_K + m * RS + h * HD;
        float d = 0.f;
        #pragma unroll
        for (int dd = 0; dd < HD; ++dd) d += qp[dd] * kp[dd];
        const float bias = sm[OFF_BIAS + (fval[n] + fval[48 - m]) * 3 + h];
        const float mask = (regid[n] != regid[m]) ? -100.f : 0.f;
        sm[idx] = d * scale + bias + mask;
    }
    __syncthreads();

    // ---- softmax: one thread per (h,n) row ----
    if (t < NH * NTOK) {
        float* row = sm + t * NTOK;
        float mx = row[0];
        #pragma unroll 7
        for (int i = 1; i < NTOK; ++i) mx = fmaxf(mx, row[i]);
        float s = 0.f;
        #pragma unroll 7
        for (int i = 0; i < NTOK; ++i) { float e = __expf(row[i] - mx); row[i] = e; s += e; }
        const float inv = 1.f / s;
        #pragma unroll 7
        for (int i = 0; i < NTOK; ++i) row[i] *= inv;
    }
    __syncthreads();

    // ---- AV: av[n][h*32+d] = sum_m attn[h][n][m] * v[m][h*32+d]  (into Q region) ----
    for (int idx = t; idx < NH * NTOK * HD; idx += THREADS) {
        const int d = idx & 31;
        const int n = (idx >> 5) % NTOK;
        const int h = idx / (HD * NTOK);
        const float* ar = sm + (h * NTOK + n) * NTOK;
        const float* vp = sm + OFF_V + h * HD + d;
        float acc = 0.f;
        #pragma unroll 7
        for (int m = 0; m < NTOK; ++m) acc += ar[m] * vp[m * RS];
        sm[OFF_Q + n * RS + h * HD + d] = acc;
    }

    // ---- proj GEMM + scatter store: out[n][j] = dot(av[n,:], proj_w[j,:]) + proj_b[j] ----
    for (int jt = 0; jt < 3; ++jt) {
        __syncthreads();
        for (int i = t; i < 32 * 96; i += THREADS)
            sm[OFF_WT + (i / 96) * RS + (i % 96)] = proj_w[jt * 32 * 96 + i];
        __syncthreads();
        const int j = jt * 32 + tj;
        float acc[7];
        const float bj = proj_b[j];
        #pragma unroll
        for (int i = 0; i < 7; ++i) acc[i] = bj;
        #pragma unroll 4
        for (int cc = 0; cc < 96; ++cc) {
            const float wv = sm[OFF_WT + tj * RS + cc];
            #pragma unroll
            for (int i = 0; i < 7; ++i)
                acc[i] += sm[OFF_Q + (tn + 8 * i) * RS + cc] * wv;
        }
        #pragma unroll
        for (int i = 0; i < 7; ++i) {
            const int n = tn + 8 * i;
            if (n < NTOK) out[rowoff[n] + j] = acc[i];
        }
    }
}

extern "C" void kernel_launch(void* const* d_in, const int* in_sizes, int n_in,
                              void* d_out, int out_size)
{
    (void)in_sizes; (void)n_in; (void)out_size;
    const float* query  = (const float*)d_in[0];
    const float* skipq  = (const float*)d_in[1];
    const float* qkv_w  = (const float*)d_in[2];
    const float* qkv_b  = (const float*)d_in[3];
    const float* skip_w = (const float*)d_in[4];
    const float* skip_b = (const float*)d_in[5];
    const float* proj_w = (const float*)d_in[6];
    const float* proj_b = (const float*)d_in[7];
    const float* btab   = (const float*)d_in[8];
    float* out = (float*)d_out;

    cudaFuncSetAttribute(swin_msa_kernel,
                         cudaFuncAttributeMaxDynamicSharedMemorySize, SMEM_BYTES);

    swin_msa_kernel<<<4 * NWIN, THREADS, SMEM_BYTES>>>(
        query, skipq, qkv_w, qkv_b, skip_w, skip_b, proj_w, proj_b, btab, out);
}

// round 3
// speedup vs baseline: 2.0081x; 2.0081x over previous
#include <cuda_runtime.h>

// ShiftWindowMSA fused kernel for GB300 (sm_103a) — round 2: 2-D register tiling
// B=4, H=W=224, C=96, window=7 (N=49), shift=3, heads=3 (hd=32)

#define NTOK    49
#define CH      96
#define NH      3
#define HD      32
#define RS      97          // activation row stride (odd -> conflict-free scalar)
#define WS      33          // weight-tile row stride (odd)
#define HP      224
#define THREADS 256

// smem float offsets
#define OA 0                // X -> K -> AVresult            (49*97 = 4753)
#define OB 4753             // SX -> Q -> proj weight tile   (4753)
#define OC 9506             // V                             (4753)
#define OD 14259            // weight k-chunks -> attn       (7203)
#define OE 21462            // rel-pos bias table            (507)
#define SMEM_FLOATS 21969
#define SMEM_BYTES  (SMEM_FLOATS * 4)

__global__ __launch_bounds__(THREADS, 2)
void swin_msa_kernel(const float* __restrict__ query,
                     const float* __restrict__ skipq,
                     const float* __restrict__ qkv_w,
                     const float* __restrict__ qkv_b,
                     const float* __restrict__ skip_w,
                     const float* __restrict__ skip_b,
                     const float* __restrict__ proj_w,
                     const float* __restrict__ proj_b,
                     const float* __restrict__ btab,
                     float* __restrict__ out)
{
    extern __shared__ float sm[];
    __shared__ int fval[NTOK];    // 13*(n/7) + n%7
    __shared__ int regid[NTOK];   // shift-mask region id
    __shared__ int rowoff[NTOK];  // gmem offset of token row (load == store)

    const int t   = threadIdx.x;
    const int blk = blockIdx.x;
    const int b   = blk >> 10;
    const int wi  = blk & 1023;
    const int wr  = wi >> 5;
    const int wc  = wi & 31;

    // ---- per-token precompute ----
    if (t < NTOK) {
        int r = t / 7, c = t - r * 7;
        fval[t] = 13 * r + c;
        int hg = wr * 7 + r;
        int wg = wc * 7 + c;
        int rh = (hg < 217) ? 0 : ((hg < 221) ? 1 : 2);
        int rw = (wg < 217) ? 0 : ((wg < 221) ? 1 : 2);
        regid[t] = rh * 3 + rw;
        int hs = hg + 3; if (hs >= HP) hs -= HP;
        int ws = wg + 3; if (ws >= HP) ws -= HP;
        rowoff[t] = (b * (HP * HP) + hs * HP + ws) * CH;
    }
    for (int i = t; i < 507; i += THREADS) sm[OE + i] = btab[i];
    __syncthreads();

    // ---- load x -> A, sx -> B ----
    {
        const int warp = t >> 5, lane = t & 31;
        for (int n = warp; n < NTOK; n += 8) {
            if (lane < 24) {
                const int base = rowoff[n];
                float4 xv = *(const float4*)(query + base + lane * 4);
                float4 sv = *(const float4*)(skipq + base + lane * 4);
                int so = n * RS + lane * 4;
                sm[OA + so + 0] = xv.x; sm[OA + so + 1] = xv.y;
                sm[OA + so + 2] = xv.z; sm[OA + so + 3] = xv.w;
                sm[OB + so + 0] = sv.x; sm[OB + so + 1] = sv.y;
                sm[OB + so + 2] = sv.z; sm[OB + so + 3] = sv.w;
            }
        }
    }

    const int tj = t & 31;   // column lane
    const int tn = t >> 5;   // row group: rows tn, tn+8, ..., tn+48

    // ================= KV GEMM: 49x192, reg tile 7x6 =================
    {
        float acc[7][6];
        #pragma unroll
        for (int g = 0; g < 6; ++g) {
            const float bj = qkv_b[tj + 32 * g];
            #pragma unroll
            for (int i = 0; i < 7; ++i) acc[i][g] = bj;
        }
        for (int ch = 0; ch < 3; ++ch) {
            __syncthreads();
            for (int i2 = t; i2 < 192 * 32; i2 += THREADS) {
                const int j = i2 >> 5, cc = i2 & 31;
                sm[OD + j * WS + cc] = qkv_w[j * CH + ch * 32 + cc];
            }
            __syncthreads();
            #pragma unroll 2
            for (int cc = 0; cc < 32; ++cc) {
                float a[7];
                #pragma unroll
                for (int i = 0; i < 7; ++i)
                    a[i] = sm[OA + (tn + 8 * i) * RS + ch * 32 + cc];
                #pragma unroll
                for (int g = 0; g < 6; ++g) {
                    const float wv = sm[OD + (tj + 32 * g) * WS + cc];
                    #pragma unroll
                    for (int i = 0; i < 7; ++i) acc[i][g] += a[i] * wv;
                }
            }
        }
        __syncthreads();
        // K (cols 0..95) overwrites X in A ; V -> C
        #pragma unroll
        for (int i = 0; i < 7; ++i) {
            const int n = tn + 8 * i;
            if (n < NTOK) {
                #pragma unroll
                for (int g = 0; g < 3; ++g) sm[OA + n * RS + tj + 32 * g] = acc[i][g];
                #pragma unroll
                for (int g = 3; g < 6; ++g) sm[OC + n * RS + tj + 32 * (g - 3)] = acc[i][g];
            }
        }
    }

    // ================= Q GEMM: 49x96, reg tile 7x3 =================
    {
        float acc[7][3];
        #pragma unroll
        for (int g = 0; g < 3; ++g) {
            const float bj = skip_b[tj + 32 * g];
            #pragma unroll
            for (int i = 0; i < 7; ++i) acc[i][g] = bj;
        }
        for (int ch = 0; ch < 3; ++ch) {
            __syncthreads();
            for (int i2 = t; i2 < 96 * 32; i2 += THREADS) {
                const int j = i2 >> 5, cc = i2 & 31;
                sm[OD + j * WS + cc] = skip_w[j * CH + ch * 32 + cc];
            }
            __syncthreads();
            #pragma unroll 2
            for (int cc = 0; cc < 32; ++cc) {
                float a[7];
                #pragma unroll
                for (int i = 0; i < 7; ++i)
                    a[i] = sm[OB + (tn + 8 * i) * RS + ch * 32 + cc];
                #pragma unroll
                for (int g = 0; g < 3; ++g) {
                    const float wv = sm[OD + (tj + 32 * g) * WS + cc];
                    #pragma unroll
                    for (int i = 0; i < 7; ++i) acc[i][g] += a[i] * wv;
                }
            }
        }
        __syncthreads();
        // Q overwrites SX in B (accumulators complete; all reads done)
        #pragma unroll
        for (int i = 0; i < 7; ++i) {
            const int n = tn + 8 * i;
            if (n < NTOK) {
                #pragma unroll
                for (int g = 0; g < 3; ++g) sm[OB + n * RS + tj + 32 * g] = acc[i][g];
            }
        }
    }
    __syncthreads();

    // ================= QK^T + bias + mask -> attn in D =================
    // 147 threads: each computes a 7x7 tile of attn[h]
    const float scale = 0.17677669529663687f;  // 1/sqrt(32)
    if (t < NH * NTOK) {
        const int h  = t / NTOK;
        const int r  = t - h * NTOK;
        const int rn = r / 7;
        const int rm = r - rn * 7;
        float s[7][7];
        #pragma unroll
        for (int i = 0; i < 7; ++i)
            #pragma unroll
            for (int j = 0; j < 7; ++j) s[i][j] = 0.f;
        const float* qb = sm + OB + rn * RS + h * HD;
        const float* kb = sm + OA + rm * RS + h * HD;
        #pragma unroll 4
        for (int k = 0; k < HD; ++k) {
            float qv[7], kv[7];
            #pragma unroll
            for (int i = 0; i < 7; ++i) qv[i] = qb[i * 7 * RS + k];
            #pragma unroll
            for (int j = 0; j < 7; ++j) kv[j] = kb[j * 7 * RS + k];
            #pragma unroll
            for (int i = 0; i < 7; ++i)
                #pragma unroll
                for (int j = 0; j < 7; ++j) s[i][j] += qv[i] * kv[j];
        }
        #pragma unroll
        for (int i = 0; i < 7; ++i) {
            const int n = rn + 7 * i;
            #pragma unroll
            for (int j = 0; j < 7; ++j) {
                const int m = rm + 7 * j;
                const float bias = sm[OE + (fval[n] + fval[48 - m]) * 3 + h];
                const float mask = (regid[n] != regid[m]) ? -100.f : 0.f;
                sm[OD + h * (NTOK * NTOK) + n * NTOK + m] = s[i][j] * scale + bias + mask;
            }
        }
    }
    __syncthreads();

    // ================= softmax (one thread per (h,n) row) =================
    if (t < NH * NTOK) {
        float* row = sm + OD + t * NTOK;
        float mx = row[0];
        #pragma unroll 7
        for (int i = 1; i < NTOK; ++i) mx = fmaxf(mx, row[i]);
        float ssum = 0.f;
        #pragma unroll 7
        for (int i = 0; i < NTOK; ++i) { float e = __expf(row[i] - mx); row[i] = e; ssum += e; }
        const float inv = 1.f / ssum;
        #pragma unroll 7
        for (int i = 0; i < NTOK; ++i) row[i] *= inv;
    }
    __syncthreads();

    // ================= AV: 49x96, reg tile 7 rows x 3 head-cols =================
    {
        float acc[7][3];
        #pragma unroll
        for (int i = 0; i < 7; ++i)
            #pragma unroll
            for (int h = 0; h < 3; ++h) acc[i][h] = 0.f;
        #pragma unroll 2
        for (int m = 0; m < NTOK; ++m) {
            float vv[3];
            #pragma unroll
            for (int h = 0; h < 3; ++h) vv[h] = sm[OC + m * RS + h * HD + tj];
            #pragma unroll
            for (int i = 0; i < 7; ++i) {
                const int n = tn + 8 * i;
                #pragma unroll
                for (int h = 0; h < 3; ++h)
                    acc[i][h] += sm[OD + h * (NTOK * NTOK) + n * NTOK + m] * vv[h];
            }
        }
        __syncthreads();
        // AV result overwrites K in A
        #pragma unroll
        for (int i = 0; i < 7; ++i) {
            const int n = tn + 8 * i;
            if (n < NTOK) {
                #pragma unroll
                for (int h = 0; h < 3; ++h) sm[OA + n * RS + h * HD + tj] = acc[i][h];
            }
        }
    }

    // ================= proj GEMM: 49x96, reg tile 7x3, store to gmem =================
    {
        float acc[7][3];
        #pragma unroll
        for (int g = 0; g < 3; ++g) {
            const float bj = proj_b[tj + 32 * g];
            #pragma unroll
            for (int i = 0; i < 7; ++i) acc[i][g] = bj;
        }
        for (int ch = 0; ch < 3; ++ch) {
            __syncthreads();
            for (int i2 = t; i2 < 96 * 32; i2 += THREADS) {
                const int j = i2 >> 5, cc = i2 & 31;
                sm[OB + j * WS + cc] = proj_w[j * CH + ch * 32 + cc];   // over dead Q
            }
            __syncthreads();
            #pragma unroll 2
            for (int cc = 0; cc < 32; ++cc) {
                float a[7];
                #pragma unroll
                for (int i = 0; i < 7; ++i)
                    a[i] = sm[OA + (tn + 8 * i) * RS + ch * 32 + cc];
                #pragma unroll
                for (int g = 0; g < 3; ++g) {
                    const float wv = sm[OB + (tj + 32 * g) * WS + cc];
                    #pragma unroll
                    for (int i = 0; i < 7; ++i) acc[i][g] += a[i] * wv;
                }
            }
        }
        #pragma unroll
        for (int i = 0; i < 7; ++i) {
            const int n = tn + 8 * i;
            if (n < NTOK) {
                #pragma unroll
                for (int g = 0; g < 3; ++g) out[rowoff[n] + tj + 32 * g] = acc[i][g];
            }
        }
    }
}

extern "C" void kernel_launch(void* const* d_in, const int* in_sizes, int n_in,
                              void* d_out, int out_size)
{
    (void)in_sizes; (void)n_in; (void)out_size;
    const float* query  = (const float*)d_in[0];
    const float* skipq  = (const float*)d_in[1];
    const float* qkv_w  = (const float*)d_in[2];
    const float* qkv_b  = (const float*)d_in[3];
    const float* skip_w = (const float*)d_in[4];
    const float* skip_b = (const float*)d_in[5];
    const float* proj_w = (const float*)d_in[6];
    const float* proj_b = (const float*)d_in[7];
    const float* btab   = (const float*)d_in[8];
    float* out = (float*)d_out;

    cudaFuncSetAttribute(swin_msa_kernel,
                         cudaFuncAttributeMaxDynamicSharedMemorySize, SMEM_BYTES);

    swin_msa_kernel<<<4 * 1024, THREADS, SMEM_BYTES>>>(
        query, skipq, qkv_w, qkv_b, skip_w, skip_b, proj_w, proj_b, btab, out);
}

// round 4
// speedup vs baseline: 2.4360x; 1.2131x over previous
#include <cuda_runtime.h>

// ShiftWindowMSA fused kernel for GB300 (sm_103a) — round 3:
// packed f32x2 FMA + vectorized LDS.128 activation/attn loads.
// B=4, H=W=224, C=96, window=7 (N=49), shift=3, heads=3 (hd=32)

#define NTOK    49
#define CH      96
#define NH      3
#define HD      32
#define RS      100         // activation row stride (mult of 4 -> 16B-aligned rows)
#define KWS     202         // KV weight tile row stride (cc-major [32][192+10])
#define QWS     106         // Q/proj weight tile row stride (cc-major [32][96+10])
#define ATS     52          // attn row stride (mult of 4)
#define HP      224
#define THREADS 256

// smem float offsets
#define OA 0                // X -> K -> AV result       (49*100 = 4900)
#define OB 4900             // SX -> Q -> proj wt tile   (4900)
#define OC 9800             // V                         (4900)
#define OD 14700            // weight tiles -> attn      (3*49*52 = 7644)
#define OE 22344            // rel-pos bias table        (507)
#define SMEM_FLOATS 22851
#define SMEM_BYTES  (SMEM_FLOATS * 4)

typedef unsigned long long u64;

__device__ __forceinline__ u64 pk2(float lo, float hi) {
    u64 r; asm("mov.b64 %0, {%1, %2};" : "=l"(r) : "f"(lo), "f"(hi)); return r;
}
__device__ __forceinline__ void upk2(u64 v, float& lo, float& hi) {
    asm("mov.b64 {%0, %1}, %2;" : "=f"(lo), "=f"(hi) : "l"(v));
}
__device__ __forceinline__ void ffma2(u64& d, u64 a, u64 b) {
    asm("fma.rn.f32x2 %0, %1, %2, %0;" : "+l"(d) : "l"(a), "l"(b));
}

__global__ __launch_bounds__(THREADS, 2)
void swin_msa_kernel(const float* __restrict__ query,
                     const float* __restrict__ skipq,
                     const float* __restrict__ qkv_w,
                     const float* __restrict__ qkv_b,
                     const float* __restrict__ skip_w,
                     const float* __restrict__ skip_b,
                     const float* __restrict__ proj_w,
                     const float* __restrict__ proj_b,
                     const float* __restrict__ btab,
                     float* __restrict__ out)
{
    extern __shared__ float sm[];
    __shared__ int fval[NTOK];
    __shared__ int regid[NTOK];
    __shared__ int rowoff[NTOK];

    const int t   = threadIdx.x;
    const int blk = blockIdx.x;
    const int b   = blk >> 10;
    const int wi  = blk & 1023;
    const int wr  = wi >> 5;
    const int wc  = wi & 31;

    if (t < NTOK) {
        int r = t / 7, c = t - r * 7;
        fval[t] = 13 * r + c;
        int hg = wr * 7 + r;
        int wg = wc * 7 + c;
        int rh = (hg < 217) ? 0 : ((hg < 221) ? 1 : 2);
        int rw = (wg < 217) ? 0 : ((wg < 221) ? 1 : 2);
        regid[t] = rh * 3 + rw;
        int hs = hg + 3; if (hs >= HP) hs -= HP;
        int ws = wg + 3; if (ws >= HP) ws -= HP;
        rowoff[t] = (b * (HP * HP) + hs * HP + ws) * CH;
    }
    for (int i = t; i < 507; i += THREADS) sm[OE + i] = btab[i];
    __syncthreads();

    // ---- load x -> A, sx -> B ----
    {
        const int warp = t >> 5, lane = t & 31;
        for (int n = warp; n < NTOK; n += 8) {
            if (lane < 24) {
                const int base = rowoff[n];
                float4 xv = *(const float4*)(query + base + lane * 4);
                float4 sv = *(const float4*)(skipq + base + lane * 4);
                *(float4*)&sm[OA + n * RS + lane * 4] = xv;
                *(float4*)&sm[OB + n * RS + lane * 4] = sv;
            }
        }
    }

    const int tj = t & 31;
    const int tn = t >> 5;

    // ================= KV GEMM: 49x192, tile 7 rows x 3 col-pairs =================
    {
        u64 acc2[7][3];
        #pragma unroll
        for (int g = 0; g < 3; ++g) {
            const int col = 2 * tj + 64 * g;
            u64 b2 = pk2(qkv_b[col], qkv_b[col + 1]);
            #pragma unroll
            for (int i = 0; i < 7; ++i) acc2[i][g] = b2;
        }
        for (int ch = 0; ch < 3; ++ch) {
            __syncthreads();
            for (int i2 = t; i2 < 192 * 32; i2 += THREADS) {
                const int j = i2 >> 5, cc = i2 & 31;
                sm[OD + cc * KWS + j] = qkv_w[j * CH + ch * 32 + cc];
            }
            __syncthreads();
            #pragma unroll 2
            for (int cq = 0; cq < 8; ++cq) {
                float4 a4[7];
                #pragma unroll
                for (int i = 0; i < 7; ++i)
                    a4[i] = *(const float4*)&sm[OA + (tn + 8 * i) * RS + ch * 32 + cq * 4];
                const float* wb = sm + OD + (cq * 4) * KWS + 2 * tj;
                #pragma unroll
                for (int q = 0; q < 4; ++q) {
                    u64 w0 = *(const u64*)(wb + q * KWS);
                    u64 w1 = *(const u64*)(wb + q * KWS + 64);
                    u64 w2 = *(const u64*)(wb + q * KWS + 128);
                    #pragma unroll
                    for (int i = 0; i < 7; ++i) {
                        const float av = (q == 0) ? a4[i].x : (q == 1) ? a4[i].y
                                       : (q == 2) ? a4[i].z : a4[i].w;
                        const u64 a2 = pk2(av, av);
                        ffma2(acc2[i][0], a2, w0);
                        ffma2(acc2[i][1], a2, w1);
                        ffma2(acc2[i][2], a2, w2);
                    }
                }
            }
        }
        __syncthreads();
        #pragma unroll
        for (int i = 0; i < 7; ++i) {
            const int n = tn + 8 * i;
            if (n < NTOK) {
                #pragma unroll
                for (int g = 0; g < 3; ++g) {
                    const int col = 2 * tj + 64 * g;
                    float lo, hi; upk2(acc2[i][g], lo, hi);
                    if (col < 96) *(float2*)&sm[OA + n * RS + col] = make_float2(lo, hi);
                    else          *(float2*)&sm[OC + n * RS + col - 96] = make_float2(lo, hi);
                }
            }
        }
    }

    // ================= Q GEMM: 49x96, cols {2tj,2tj+1} pair + {64+tj} scalar =================
    {
        u64 accp[7]; float accs[7];
        {
            u64 b2 = pk2(skip_b[2 * tj], skip_b[2 * tj + 1]);
            const float bs = skip_b[64 + tj];
            #pragma unroll
            for (int i = 0; i < 7; ++i) { accp[i] = b2; accs[i] = bs; }
        }
        for (int ch = 0; ch < 3; ++ch) {
            __syncthreads();
            for (int i2 = t; i2 < 96 * 32; i2 += THREADS) {
                const int j = i2 >> 5, cc = i2 & 31;
                sm[OD + cc * QWS + j] = skip_w[j * CH + ch * 32 + cc];
            }
            __syncthreads();
            #pragma unroll 2
            for (int cq = 0; cq < 8; ++cq) {
                float4 a4[7];
                #pragma unroll
                for (int i = 0; i < 7; ++i)
                    a4[i] = *(const float4*)&sm[OB + (tn + 8 * i) * RS + ch * 32 + cq * 4];
                const float* wb = sm + OD + (cq * 4) * QWS;
                #pragma unroll
                for (int q = 0; q < 4; ++q) {
                    u64 w2 = *(const u64*)(wb + q * QWS + 2 * tj);
                    float ws = wb[q * QWS + 64 + tj];
                    #pragma unroll
                    for (int i = 0; i < 7; ++i) {
                        const float av = (q == 0) ? a4[i].x : (q == 1) ? a4[i].y
                                       : (q == 2) ? a4[i].z : a4[i].w;
                        ffma2(accp[i], pk2(av, av), w2);
                        accs[i] += av * ws;
                    }
                }
            }
        }
        __syncthreads();
        #pragma unroll
        for (int i = 0; i < 7; ++i) {
            const int n = tn + 8 * i;
            if (n < NTOK) {
                float lo, hi; upk2(accp[i], lo, hi);
                *(float2*)&sm[OB + n * RS + 2 * tj] = make_float2(lo, hi);
                sm[OB + n * RS + 64 + tj] = accs[i];
            }
        }
    }
    __syncthreads();

    // ================= QK^T + bias + mask -> attn (stride ATS) =================
    const float scale = 0.17677669529663687f;
    if (t < NH * NTOK) {
        const int h  = t / NTOK;
        const int r  = t - h * NTOK;
        const int rn = r / 7;
        const int rm = r - rn * 7;
        float s[7][7];
        #pragma unroll
        for (int i = 0; i < 7; ++i)
            #pragma unroll
            for (int j = 0; j < 7; ++j) s[i][j] = 0.f;
        const float* qb = sm + OB + rn * RS + h * HD;
        const float* kb = sm + OA + rm * RS + h * HD;
        #pragma unroll
        for (int kq = 0; kq < 8; ++kq) {
            float4 k4[7];
            #pragma unroll
            for (int j = 0; j < 7; ++j) k4[j] = *(const float4*)(kb + j * 7 * RS + kq * 4);
            #pragma unroll
            for (int i = 0; i < 7; ++i) {
                float4 q4 = *(const float4*)(qb + i * 7 * RS + kq * 4);
                #pragma unroll
                for (int j = 0; j < 7; ++j)
                    s[i][j] += q4.x * k4[j].x + q4.y * k4[j].y + q4.z * k4[j].z + q4.w * k4[j].w;
            }
        }
        #pragma unroll
        for (int i = 0; i < 7; ++i) {
            const int n = rn + 7 * i;
            #pragma unroll
            for (int j = 0; j < 7; ++j) {
                const int m = rm + 7 * j;
                const float bias = sm[OE + (fval[n] + fval[48 - m]) * 3 + h];
                const float mask = (regid[n] != regid[m]) ? -100.f : 0.f;
                sm[OD + h * (NTOK * ATS) + n * ATS + m] = s[i][j] * scale + bias + mask;
            }
        }
    }
    __syncthreads();

    // ================= softmax =================
    if (t < NH * NTOK) {
        float* row = sm + OD + (t / NTOK) * (NTOK * ATS) + (t % NTOK) * ATS;
        float rv[49];
        #pragma unroll
        for (int q = 0; q < 12; ++q) {
            float4 v = *(const float4*)(row + 4 * q);
            rv[4 * q] = v.x; rv[4 * q + 1] = v.y; rv[4 * q + 2] = v.z; rv[4 * q + 3] = v.w;
        }
        rv[48] = row[48];
        float mx = rv[0];
        #pragma unroll
        for (int i = 1; i < 49; ++i) mx = fmaxf(mx, rv[i]);
        float ssum = 0.f;
        #pragma unroll
        for (int i = 0; i < 49; ++i) { rv[i] = __expf(rv[i] - mx); ssum += rv[i]; }
        const float inv = 1.f / ssum;
        #pragma unroll
        for (int q = 0; q < 12; ++q)
            *(float4*)(row + 4 * q) = make_float4(rv[4*q] * inv, rv[4*q+1] * inv,
                                                 rv[4*q+2] * inv, rv[4*q+3] * inv);
        row[48] = rv[48] * inv;
    }
    __syncthreads();

    // ================= AV: dual-accumulator f32x2 over m =================
    {
        u64 acc2[7][3];
        #pragma unroll
        for (int i = 0; i < 7; ++i)
            #pragma unroll
            for (int h = 0; h < 3; ++h) acc2[i][h] = pk2(0.f, 0.f);
        #pragma unroll 2
        for (int mq = 0; mq < 12; ++mq) {
            const int m0 = 4 * mq;
            u64 va[3], vb[3];
            #pragma unroll
            for (int h = 0; h < 3; ++h) {
                const int vc = h * HD + tj;
                va[h] = pk2(sm[OC + m0 * RS + vc],       sm[OC + (m0 + 1) * RS + vc]);
                vb[h] = pk2(sm[OC + (m0 + 2) * RS + vc], sm[OC + (m0 + 3) * RS + vc]);
            }
            #pragma unroll
            for (int i = 0; i < 7; ++i) {
                const int n = tn + 8 * i;
                #pragma unroll
                for (int h = 0; h < 3; ++h) {
                    float4 a4 = *(const float4*)&sm[OD + h * (NTOK * ATS) + n * ATS + m0];
                    ffma2(acc2[i][h], pk2(a4.x, a4.y), va[h]);
                    ffma2(acc2[i][h], pk2(a4.z, a4.w), vb[h]);
                }
            }
        }
        {   // tail m = 48 (lo half only)
            float vt[3];
            #pragma unroll
            for (int h = 0; h < 3; ++h) vt[h] = sm[OC + 48 * RS + h * HD + tj];
            #pragma unroll
            for (int i = 0; i < 7; ++i) {
                const int n = tn + 8 * i;
                #pragma unroll
                for (int h = 0; h < 3; ++h) {
                    const float at = sm[OD + h * (NTOK * ATS) + n * ATS + 48];
                    ffma2(acc2[i][h], pk2(at, 0.f), pk2(vt[h], 0.f));
                }
            }
        }
        #pragma unroll
        for (int i = 0; i < 7; ++i) {
            const int n = tn + 8 * i;
            if (n < NTOK) {
                #pragma unroll
                for (int h = 0; h < 3; ++h) {
                    float lo, hi; upk2(acc2[i][h], lo, hi);
                    sm[OA + n * RS + h * HD + tj] = lo + hi;
                }
            }
        }
    }

    // ================= proj GEMM (reads A, wt tile in B, stores gmem) =================
    {
        u64 accp[7]; float accs[7];
        {
            u64 b2 = pk2(proj_b[2 * tj], proj_b[2 * tj + 1]);
            const float bs = proj_b[64 + tj];
            #pragma unroll
            for (int i = 0; i < 7; ++i) { accp[i] = b2; accs[i] = bs; }
        }
        for (int ch = 0; ch < 3; ++ch) {
            __syncthreads();
            for (int i2 = t; i2 < 96 * 32; i2 += THREADS) {
                const int j = i2 >> 5, cc = i2 & 31;
                sm[OB + cc * QWS + j] = proj_w[j * CH + ch * 32 + cc];
            }
            __syncthreads();
            #pragma unroll 2
            for (int cq = 0; cq < 8; ++cq) {
                float4 a4[7];
                #pragma unroll
                for (int i = 0; i < 7; ++i)
                    a4[i] = *(const float4*)&sm[OA + (tn + 8 * i) * RS + ch * 32 + cq * 4];
                const float* wb = sm + OB + (cq * 4) * QWS;
                #pragma unroll
                for (int q = 0; q < 4; ++q) {
                    u64 w2 = *(const u64*)(wb + q * QWS + 2 * tj);
                    float ws = wb[q * QWS + 64 + tj];
                    #pragma unroll
                    for (int i = 0; i < 7; ++i) {
                        const float av = (q == 0) ? a4[i].x : (q == 1) ? a4[i].y
                                       : (q == 2) ? a4[i].z : a4[i].w;
                        ffma2(accp[i], pk2(av, av), w2);
                        accs[i] += av * ws;
                    }
                }
            }
        }
        #pragma unroll
        for (int i = 0; i < 7; ++i) {
            const int n = tn + 8 * i;
            if (n < NTOK) {
                float lo, hi; upk2(accp[i], lo, hi);
                *(float2*)(out + rowoff[n] + 2 * tj) = make_float2(lo, hi);
                out[rowoff[n] + 64 + tj] = accs[i];
            }
        }
    }
}

extern "C" void kernel_launch(void* const* d_in, const int* in_sizes, int n_in,
                              void* d_out, int out_size)
{
    (void)in_sizes; (void)n_in; (void)out_size;
    const float* query  = (const float*)d_in[0];
    const float* skipq  = (const float*)d_in[1];
    const float* qkv_w  = (const float*)d_in[2];
    const float* qkv_b  = (const float*)d_in[3];
    const float* skip_w = (const float*)d_in[4];
    const float* skip_b = (const float*)d_in[5];
    const float* proj_w = (const float*)d_in[6];
    const float* proj_b = (const float*)d_in[7];
    const float* btab   = (const float*)d_in[8];
    float* out = (float*)d_out;

    cudaFuncSetAttribute(swin_msa_kernel,
                         cudaFuncAttributeMaxDynamicSharedMemorySize, SMEM_BYTES);

    swin_msa_kernel<<<4 * 1024, THREADS, SMEM_BYTES>>>(
        query, skipq, qkv_w, qkv_b, skip_w, skip_b, proj_w, proj_b, btab, out);
}